// round 1
// baseline (speedup 1.0000x reference)
#include <cuda_runtime.h>
#include <math.h>

// Problem constants (shapes are fixed by the dataset; runtime sizes derived from in_sizes)
#define HID 128
#define NG  50
#define MT  128        // row tile for GEMMs / edge tile
#define NTH 256

// Scratch (static device arrays — no allocation allowed)
__device__ float g_h  [40000 * 128];
__device__ float g_agg[40000 * 128];
__device__ float g_h2 [40000 * 128];

__device__ __forceinline__ float sspf(float x) {
    // softplus(x) - ln(2), numerically stable
    return fmaxf(x, 0.f) + log1pf(expf(-fabsf(x))) - 0.69314718055994530942f;
}

// ---------------------------------------------------------------------------
// C[M,128] = act(A[M,128] @ W[128,128]^T + bias), optional zeroing of zbuf tile.
// 256 threads, 128-row tile, 8x8 register microtile per thread.
// smem: sA[128][132] row-major, sB[128][132] k-major (B transposed on load).
// ---------------------------------------------------------------------------
__global__ __launch_bounds__(NTH, 1) void gemm128_kernel(
    const float* __restrict__ A, const float* __restrict__ W,
    const float* __restrict__ bias, float* __restrict__ C,
    int M, int act, float* __restrict__ zbuf)
{
    extern __shared__ float sm[];
    float (*sA)[132] = (float(*)[132])(sm);
    float (*sB)[132] = (float(*)[132])(sm + 128 * 132);

    const int tid  = threadIdx.x;
    const int row0 = blockIdx.x * MT;

    // Load W transposed into k-major smem (coalesced global reads)
    for (int idx = tid; idx < 128 * 128; idx += NTH) {
        int k = idx & 127, f = idx >> 7;
        sB[k][f] = W[idx];            // W[f*128+k]
    }
    // Load A tile (row-major, padded)
    for (int idx = tid; idx < MT * 128; idx += NTH) {
        int k = idx & 127, r = idx >> 7;
        int gr = row0 + r;
        sA[r][k] = (gr < M) ? A[(size_t)gr * 128 + k] : 0.f;
    }
    __syncthreads();

    const int tx = tid & 15;       // feature group (8 feats each)
    const int ty = tid >> 4;       // row group (8 rows each)

    float acc[8][8];
    #pragma unroll
    for (int i = 0; i < 8; i++)
        #pragma unroll
        for (int j = 0; j < 8; j++) acc[i][j] = 0.f;

    #pragma unroll 4
    for (int k = 0; k < 128; ++k) {
        float a[8];
        #pragma unroll
        for (int i = 0; i < 8; i++) a[i] = sA[ty * 8 + i][k];
        float4 b0 = *reinterpret_cast<const float4*>(&sB[k][tx * 8]);
        float4 b1 = *reinterpret_cast<const float4*>(&sB[k][tx * 8 + 4]);
        float b[8] = {b0.x, b0.y, b0.z, b0.w, b1.x, b1.y, b1.z, b1.w};
        #pragma unroll
        for (int i = 0; i < 8; i++)
            #pragma unroll
            for (int j = 0; j < 8; j++)
                acc[i][j] = fmaf(a[i], b[j], acc[i][j]);
    }

    float bb[8];
    if (bias) {
        float4 c0 = *reinterpret_cast<const float4*>(bias + tx * 8);
        float4 c1 = *reinterpret_cast<const float4*>(bias + tx * 8 + 4);
        bb[0]=c0.x; bb[1]=c0.y; bb[2]=c0.z; bb[3]=c0.w;
        bb[4]=c1.x; bb[5]=c1.y; bb[6]=c1.z; bb[7]=c1.w;
    } else {
        #pragma unroll
        for (int j = 0; j < 8; j++) bb[j] = 0.f;
    }

    #pragma unroll
    for (int i = 0; i < 8; i++) {
        int r = row0 + ty * 8 + i;
        if (r < M) {
            float v[8];
            #pragma unroll
            for (int j = 0; j < 8; j++) {
                float t = acc[i][j] + bb[j];
                v[j] = act ? sspf(t) : t;
            }
            float4* cp = reinterpret_cast<float4*>(C + (size_t)r * 128 + tx * 8);
            cp[0] = make_float4(v[0], v[1], v[2], v[3]);
            cp[1] = make_float4(v[4], v[5], v[6], v[7]);
            if (zbuf) {
                float4* zp = reinterpret_cast<float4*>(zbuf + (size_t)r * 128 + tx * 8);
                zp[0] = make_float4(0.f, 0.f, 0.f, 0.f);
                zp[1] = make_float4(0.f, 0.f, 0.f, 0.f);
            }
        }
    }
}

// ---------------------------------------------------------------------------
// Fused edge kernel: per 128-edge tile:
//   T = ssp(EA @ w1^T + b1)       (128 x 128, K=50)
//   Wf = (T @ w2^T + b2) * C(e)   (128 x 128, K=128)
//   msg = h[src] * Wf ;  atomicAdd to agg[dst]
// ---------------------------------------------------------------------------
__global__ __launch_bounds__(NTH, 1) void edge_kernel(
    const float* __restrict__ ea, const int* __restrict__ ei,
    const float* __restrict__ ew,
    const float* __restrict__ w1, const float* __restrict__ b1,
    const float* __restrict__ w2, const float* __restrict__ b2,
    const float* __restrict__ h,  float* __restrict__ agg, int E)
{
    extern __shared__ float sm[];
    // smem layout (float offsets)
    float (*sEA)[52]  = (float(*)[52])(sm);                         // 128*52  = 6656
    float (*sW1)[132] = (float(*)[132])(sm + 6656);                 // 50*132  = 6600
    float (*sW2)[132] = (float(*)[132])(sm + 6656 + 6600);          // 128*132 = 16896
    float (*sT)[132]  = (float(*)[132])(sm + 6656 + 6600 + 16896);  // 128*132 = 16896
    float* sC   = sm + 6656 + 6600 + 16896 + 16896;                 // 128
    int*   sSrc = (int*)(sC + 128);                                 // 128
    int*   sDst = sSrc + 128;                                       // 128

    const int tid = threadIdx.x;
    const int e0  = blockIdx.x * MT;

    // Edge metadata + cosine cutoff
    if (tid < 128) {
        int e = e0 + tid;
        if (e < E) {
            sSrc[tid] = ei[e];
            sDst[tid] = ei[E + e];
            float w = ew[e];
            sC[tid] = 0.5f * (cosf(w * 0.314159265358979f) + 1.f);
        } else {
            sSrc[tid] = 0; sDst[tid] = 0; sC[tid] = 0.f;
        }
    }
    // edge_attr tile (row-major, pad to 52)
    for (int idx = tid; idx < 128 * NG; idx += NTH) {
        int g = idx % NG, e = idx / NG;
        sEA[e][g] = (e0 + e < E) ? ea[(size_t)e0 * NG + idx] : 0.f;
    }
    // w1 transposed to k-major [g][f]
    for (int idx = tid; idx < 128 * NG; idx += NTH) {
        int g = idx % NG, f = idx / NG;
        sW1[g][f] = w1[idx];          // w1[f*50+g]
    }
    // w2 transposed to k-major [f][f2]
    for (int idx = tid; idx < 128 * 128; idx += NTH) {
        int k = idx & 127, f = idx >> 7;
        sW2[k][f] = w2[idx];          // w2[f*128+k]
    }
    __syncthreads();

    const int tx = tid & 15;   // feature group
    const int ty = tid >> 4;   // edge group

    // ---------------- GEMM1: T = ssp(EA @ w1^T + b1) ----------------
    float acc[8][8];
    #pragma unroll
    for (int i = 0; i < 8; i++)
        #pragma unroll
        for (int j = 0; j < 8; j++) acc[i][j] = 0.f;

    #pragma unroll 2
    for (int k = 0; k < NG; ++k) {
        float a[8];
        #pragma unroll
        for (int i = 0; i < 8; i++) a[i] = sEA[ty * 8 + i][k];
        float4 b0 = *reinterpret_cast<const float4*>(&sW1[k][tx * 8]);
        float4 b1v = *reinterpret_cast<const float4*>(&sW1[k][tx * 8 + 4]);
        float b[8] = {b0.x, b0.y, b0.z, b0.w, b1v.x, b1v.y, b1v.z, b1v.w};
        #pragma unroll
        for (int i = 0; i < 8; i++)
            #pragma unroll
            for (int j = 0; j < 8; j++)
                acc[i][j] = fmaf(a[i], b[j], acc[i][j]);
    }

    {
        float4 c0 = *reinterpret_cast<const float4*>(b1 + tx * 8);
        float4 c1 = *reinterpret_cast<const float4*>(b1 + tx * 8 + 4);
        float bb[8] = {c0.x, c0.y, c0.z, c0.w, c1.x, c1.y, c1.z, c1.w};
        #pragma unroll
        for (int i = 0; i < 8; i++) {
            float v[8];
            #pragma unroll
            for (int j = 0; j < 8; j++) v[j] = sspf(acc[i][j] + bb[j]);
            float4* tp = reinterpret_cast<float4*>(&sT[ty * 8 + i][tx * 8]);
            tp[0] = make_float4(v[0], v[1], v[2], v[3]);
            tp[1] = make_float4(v[4], v[5], v[6], v[7]);
        }
    }
    __syncthreads();

    // ---------------- GEMM2: Wf = T @ w2^T + b2 ----------------
    #pragma unroll
    for (int i = 0; i < 8; i++)
        #pragma unroll
        for (int j = 0; j < 8; j++) acc[i][j] = 0.f;

    #pragma unroll 4
    for (int k = 0; k < 128; ++k) {
        float a[8];
        #pragma unroll
        for (int i = 0; i < 8; i++) a[i] = sT[ty * 8 + i][k];
        float4 b0 = *reinterpret_cast<const float4*>(&sW2[k][tx * 8]);
        float4 b1v = *reinterpret_cast<const float4*>(&sW2[k][tx * 8 + 4]);
        float b[8] = {b0.x, b0.y, b0.z, b0.w, b1v.x, b1v.y, b1v.z, b1v.w};
        #pragma unroll
        for (int i = 0; i < 8; i++)
            #pragma unroll
            for (int j = 0; j < 8; j++)
                acc[i][j] = fmaf(a[i], b[j], acc[i][j]);
    }

    // ---------------- Epilogue: cutoff * gather * scatter-add ----------------
    float bb[8];
    {
        float4 c0 = *reinterpret_cast<const float4*>(b2 + tx * 8);
        float4 c1 = *reinterpret_cast<const float4*>(b2 + tx * 8 + 4);
        bb[0]=c0.x; bb[1]=c0.y; bb[2]=c0.z; bb[3]=c0.w;
        bb[4]=c1.x; bb[5]=c1.y; bb[6]=c1.z; bb[7]=c1.w;
    }

    #pragma unroll
    for (int i = 0; i < 8; i++) {
        int e = ty * 8 + i;
        if (e0 + e >= E) continue;
        int   s = sSrc[e];
        int   d = sDst[e];
        float c = sC[e];
        const float4* hp = reinterpret_cast<const float4*>(h + (size_t)s * 128 + tx * 8);
        float4 h0 = hp[0];
        float4 h1 = hp[1];
        float* ap = agg + (size_t)d * 128 + tx * 8;
        atomicAdd(ap + 0, (acc[i][0] + bb[0]) * c * h0.x);
        atomicAdd(ap + 1, (acc[i][1] + bb[1]) * c * h0.y);
        atomicAdd(ap + 2, (acc[i][2] + bb[2]) * c * h0.z);
        atomicAdd(ap + 3, (acc[i][3] + bb[3]) * c * h0.w);
        atomicAdd(ap + 4, (acc[i][4] + bb[4]) * c * h1.x);
        atomicAdd(ap + 5, (acc[i][5] + bb[5]) * c * h1.y);
        atomicAdd(ap + 6, (acc[i][6] + bb[6]) * c * h1.z);
        atomicAdd(ap + 7, (acc[i][7] + bb[7]) * c * h1.w);
    }
}

// ---------------------------------------------------------------------------
extern "C" void kernel_launch(void* const* d_in, const int* in_sizes, int n_in,
                              void* d_out, int out_size)
{
    const float* x   = (const float*)d_in[0];
    const int*   ei  = (const int*)  d_in[1];
    const float* ew  = (const float*)d_in[2];
    const float* ea  = (const float*)d_in[3];
    const float* mw1 = (const float*)d_in[4];
    const float* mb1 = (const float*)d_in[5];
    const float* mw2 = (const float*)d_in[6];
    const float* mb2 = (const float*)d_in[7];
    const float* l1w = (const float*)d_in[8];
    const float* l2w = (const float*)d_in[9];
    const float* l2b = (const float*)d_in[10];
    const float* lw  = (const float*)d_in[11];
    const float* lb  = (const float*)d_in[12];
    float* out = (float*)d_out;

    const int N = in_sizes[0] / 128;
    const int E = in_sizes[1] / 2;

    void* p;
    cudaGetSymbolAddress(&p, g_h);   float* h_buf   = (float*)p;
    cudaGetSymbolAddress(&p, g_agg); float* agg_buf = (float*)p;
    cudaGetSymbolAddress(&p, g_h2);  float* h2_buf  = (float*)p;

    const size_t smemG = (size_t)2 * 128 * 132 * sizeof(float);               // 135168
    const size_t smemE = (size_t)(6656 + 6600 + 16896 + 16896 + 128) * 4 + 256 * 4; // ~189.8 KB

    cudaFuncSetAttribute(gemm128_kernel, cudaFuncAttributeMaxDynamicSharedMemorySize, (int)smemG);
    cudaFuncSetAttribute(edge_kernel,    cudaFuncAttributeMaxDynamicSharedMemorySize, (int)smemE);

    const int nb  = (N + MT - 1) / MT;   // 313
    const int neb = (E + MT - 1) / MT;   // 5000

    // 1) h = x @ lin1^T ; zero agg
    gemm128_kernel<<<nb, NTH, smemG>>>(x, l1w, nullptr, h_buf, N, 0, agg_buf);
    // 2) fused edge filter + message + scatter
    edge_kernel<<<neb, NTH, smemE>>>(ea, ei, ew, mw1, mb1, mw2, mb2, h_buf, agg_buf, E);
    // 3) h2 = ssp(agg @ lin2^T + b)
    gemm128_kernel<<<nb, NTH, smemG>>>(agg_buf, l2w, l2b, h2_buf, N, 1, nullptr);
    // 4) out = h2 @ lin_w^T + lin_b
    gemm128_kernel<<<nb, NTH, smemG>>>(h2_buf, lw, lb, out, N, 0, nullptr);
}

// round 3
// speedup vs baseline: 1.9939x; 1.9939x over previous
#include <cuda_runtime.h>
#include <math.h>

#define HID 128
#define NG  50
#define MT  128
#define NTH 256

typedef unsigned long long u64;

// Scratch (static device arrays — allocation is forbidden)
__device__ float g_h  [40000 * 128];
__device__ float g_agg[40000 * 128];
__device__ float g_h2 [40000 * 128];

__device__ __forceinline__ float sspf(float x) {
    return fmaxf(x, 0.f) + log1pf(expf(-fabsf(x))) - 0.69314718055994530942f;
}

// ---- packed fp32x2 helpers (Blackwell FFMA2 pipe) ----
__device__ __forceinline__ u64 dup2(float v) {
    u64 r; asm("mov.b64 %0, {%1,%2};" : "=l"(r) : "f"(v), "f"(v)); return r;
}
__device__ __forceinline__ u64 fma2(u64 a, u64 b, u64 c) {
    u64 d; asm("fma.rn.f32x2 %0, %1, %2, %3;" : "=l"(d) : "l"(a), "l"(b), "l"(c)); return d;
}
__device__ __forceinline__ float2 unp2(u64 v) {
    float lo, hi; asm("mov.b64 {%0,%1}, %2;" : "=f"(lo), "=f"(hi) : "l"(v));
    return make_float2(lo, hi);
}
__device__ __forceinline__ void red4(float* p, float a, float b, float c, float d) {
    asm volatile("red.global.add.v4.f32 [%0], {%1,%2,%3,%4};"
                 :: "l"(p), "f"(a), "f"(b), "f"(c), "f"(d) : "memory");
}

// ---------------------------------------------------------------------------
// C[M,128] = act(A[M,128] @ W[128,128]^T + bias) with packed fp32x2 math.
// ---------------------------------------------------------------------------
__global__ __launch_bounds__(NTH, 1) void gemm128_kernel(
    const float* __restrict__ A, const float* __restrict__ W,
    const float* __restrict__ bias, float* __restrict__ C,
    int M, int act, float* __restrict__ zbuf)
{
    extern __shared__ float sm[];
    float (*sA)[132] = (float(*)[132])(sm);
    float (*sB)[132] = (float(*)[132])(sm + 128 * 132);

    const int tid  = threadIdx.x;
    const int row0 = blockIdx.x * MT;

    for (int idx = tid; idx < 128 * 128; idx += NTH) {
        int k = idx & 127, f = idx >> 7;
        sB[k][f] = W[idx];
    }
    for (int idx = tid; idx < MT * 128; idx += NTH) {
        int k = idx & 127, r = idx >> 7;
        int gr = row0 + r;
        sA[r][k] = (gr < M) ? A[(size_t)gr * 128 + k] : 0.f;
    }
    __syncthreads();

    const int tx = tid & 15;
    const int ty = tid >> 4;

    u64 acc[8][4];
    #pragma unroll
    for (int i = 0; i < 8; i++)
        #pragma unroll
        for (int j = 0; j < 4; j++) acc[i][j] = 0ull;

    #pragma unroll 4
    for (int k = 0; k < 128; ++k) {
        u64 ad[8];
        #pragma unroll
        for (int i = 0; i < 8; i++) ad[i] = dup2(sA[ty * 8 + i][k]);
        ulonglong2 q0 = *reinterpret_cast<const ulonglong2*>(&sB[k][tx * 8]);
        ulonglong2 q1 = *reinterpret_cast<const ulonglong2*>(&sB[k][tx * 8 + 4]);
        u64 bp[4] = {q0.x, q0.y, q1.x, q1.y};
        #pragma unroll
        for (int i = 0; i < 8; i++)
            #pragma unroll
            for (int j = 0; j < 4; j++)
                acc[i][j] = fma2(ad[i], bp[j], acc[i][j]);
    }

    float bb[8];
    if (bias) {
        float4 c0 = *reinterpret_cast<const float4*>(bias + tx * 8);
        float4 c1 = *reinterpret_cast<const float4*>(bias + tx * 8 + 4);
        bb[0]=c0.x; bb[1]=c0.y; bb[2]=c0.z; bb[3]=c0.w;
        bb[4]=c1.x; bb[5]=c1.y; bb[6]=c1.z; bb[7]=c1.w;
    } else {
        #pragma unroll
        for (int j = 0; j < 8; j++) bb[j] = 0.f;
    }

    #pragma unroll
    for (int i = 0; i < 8; i++) {
        int r = row0 + ty * 8 + i;
        if (r < M) {
            float v[8];
            #pragma unroll
            for (int j = 0; j < 4; j++) {
                float2 p = unp2(acc[i][j]);
                float t0 = p.x + bb[2*j], t1 = p.y + bb[2*j+1];
                v[2*j]   = act ? sspf(t0) : t0;
                v[2*j+1] = act ? sspf(t1) : t1;
            }
            float4* cp = reinterpret_cast<float4*>(C + (size_t)r * 128 + tx * 8);
            cp[0] = make_float4(v[0], v[1], v[2], v[3]);
            cp[1] = make_float4(v[4], v[5], v[6], v[7]);
            if (zbuf) {
                float4* zp = reinterpret_cast<float4*>(zbuf + (size_t)r * 128 + tx * 8);
                zp[0] = make_float4(0.f, 0.f, 0.f, 0.f);
                zp[1] = make_float4(0.f, 0.f, 0.f, 0.f);
            }
        }
    }
}

// ---------------------------------------------------------------------------
// Persistent fused edge kernel. Weights staged in smem ONCE per block; loop
// over 128-edge tiles:
//   T = ssp(EA @ w1^T + b1); Wf = (T @ w2^T + b2)*C; msg = h[src]*Wf -> red agg[dst]
// ---------------------------------------------------------------------------
__global__ __launch_bounds__(NTH, 1) void edge_kernel(
    const float* __restrict__ ea, const int* __restrict__ ei,
    const float* __restrict__ ew,
    const float* __restrict__ w1, const float* __restrict__ b1,
    const float* __restrict__ w2, const float* __restrict__ b2,
    const float* __restrict__ h,  float* __restrict__ agg,
    int E, int nTiles)
{
    extern __shared__ float sm[];
    float (*sEA)[52]  = (float(*)[52])(sm);                         // 128*52
    float (*sW1)[132] = (float(*)[132])(sm + 6656);                 // 50*132
    float (*sW2)[132] = (float(*)[132])(sm + 6656 + 6600);          // 128*132
    float (*sT)[132]  = (float(*)[132])(sm + 6656 + 6600 + 16896);  // 128*132
    float* sC   = sm + 6656 + 6600 + 16896 + 16896;
    int*   sSrc = (int*)(sC + 128);
    int*   sDst = sSrc + 128;

    const int tid = threadIdx.x;
    const int tx  = tid & 15;
    const int ty  = tid >> 4;

    // ---- one-time weight staging (transposed to k-major) ----
    for (int idx = tid; idx < 128 * NG; idx += NTH) {
        int g = idx % NG, f = idx / NG;
        sW1[g][f] = w1[idx];
    }
    for (int idx = tid; idx < 128 * 128; idx += NTH) {
        int k = idx & 127, f = idx >> 7;
        sW2[k][f] = w2[idx];
    }

    // bias registers (persist across tiles)
    float bb1[8], bb2[8];
    {
        float4 c0 = *reinterpret_cast<const float4*>(b1 + tx * 8);
        float4 c1 = *reinterpret_cast<const float4*>(b1 + tx * 8 + 4);
        bb1[0]=c0.x; bb1[1]=c0.y; bb1[2]=c0.z; bb1[3]=c0.w;
        bb1[4]=c1.x; bb1[5]=c1.y; bb1[6]=c1.z; bb1[7]=c1.w;
        float4 d0 = *reinterpret_cast<const float4*>(b2 + tx * 8);
        float4 d1 = *reinterpret_cast<const float4*>(b2 + tx * 8 + 4);
        bb2[0]=d0.x; bb2[1]=d0.y; bb2[2]=d0.z; bb2[3]=d0.w;
        bb2[4]=d1.x; bb2[5]=d1.y; bb2[6]=d1.z; bb2[7]=d1.w;
    }

    for (int t = blockIdx.x; t < nTiles; t += gridDim.x) {
        const int e0 = t * MT;

        // ---- tile staging ----
        if (tid < 128) {
            int e = e0 + tid;
            if (e < E) {
                sSrc[tid] = ei[e];
                sDst[tid] = ei[E + e];
                sC[tid] = 0.5f * (cosf(ew[e] * 0.31415926535897932f) + 1.f);
            } else { sSrc[tid] = 0; sDst[tid] = 0; sC[tid] = 0.f; }
        }
        for (int idx = tid; idx < 128 * NG; idx += NTH) {
            int g = idx % NG, e = idx / NG;
            sEA[e][g] = (e0 + e < E) ? ea[(size_t)e0 * NG + idx] : 0.f;
        }
        __syncthreads();

        // ---- GEMM1: T = ssp(EA @ w1^T + b1), K = 50 ----
        u64 acc[8][4];
        #pragma unroll
        for (int i = 0; i < 8; i++)
            #pragma unroll
            for (int j = 0; j < 4; j++) acc[i][j] = 0ull;

        #pragma unroll 2
        for (int k = 0; k < NG; ++k) {
            u64 ad[8];
            #pragma unroll
            for (int i = 0; i < 8; i++) ad[i] = dup2(sEA[ty * 8 + i][k]);
            ulonglong2 q0 = *reinterpret_cast<const ulonglong2*>(&sW1[k][tx * 8]);
            ulonglong2 q1 = *reinterpret_cast<const ulonglong2*>(&sW1[k][tx * 8 + 4]);
            u64 bp[4] = {q0.x, q0.y, q1.x, q1.y};
            #pragma unroll
            for (int i = 0; i < 8; i++)
                #pragma unroll
                for (int j = 0; j < 4; j++)
                    acc[i][j] = fma2(ad[i], bp[j], acc[i][j]);
        }

        #pragma unroll
        for (int i = 0; i < 8; i++) {
            float v[8];
            #pragma unroll
            for (int j = 0; j < 4; j++) {
                float2 p = unp2(acc[i][j]);
                v[2*j]   = sspf(p.x + bb1[2*j]);
                v[2*j+1] = sspf(p.y + bb1[2*j+1]);
            }
            float4* tp = reinterpret_cast<float4*>(&sT[ty * 8 + i][tx * 8]);
            tp[0] = make_float4(v[0], v[1], v[2], v[3]);
            tp[1] = make_float4(v[4], v[5], v[6], v[7]);
        }
        __syncthreads();

        // ---- GEMM2: Wf = T @ w2^T + b2, K = 128 ----
        #pragma unroll
        for (int i = 0; i < 8; i++)
            #pragma unroll
            for (int j = 0; j < 4; j++) acc[i][j] = 0ull;

        #pragma unroll 4
        for (int k = 0; k < 128; ++k) {
            u64 ad[8];
            #pragma unroll
            for (int i = 0; i < 8; i++) ad[i] = dup2(sT[ty * 8 + i][k]);
            ulonglong2 q0 = *reinterpret_cast<const ulonglong2*>(&sW2[k][tx * 8]);
            ulonglong2 q1 = *reinterpret_cast<const ulonglong2*>(&sW2[k][tx * 8 + 4]);
            u64 bp[4] = {q0.x, q0.y, q1.x, q1.y};
            #pragma unroll
            for (int i = 0; i < 8; i++)
                #pragma unroll
                for (int j = 0; j < 4; j++)
                    acc[i][j] = fma2(ad[i], bp[j], acc[i][j]);
        }

        // ---- epilogue: cutoff * gather(h[src]) -> red.v4 into agg[dst] ----
        #pragma unroll
        for (int i = 0; i < 8; i++) {
            int e = ty * 8 + i;
            if (e0 + e >= E) continue;
            int   s = sSrc[e];
            int   d = sDst[e];
            float c = sC[e];
            const float4* hp = reinterpret_cast<const float4*>(h + (size_t)s * 128 + tx * 8);
            float4 h0 = hp[0];
            float4 h1 = hp[1];
            float* ap = agg + (size_t)d * 128 + tx * 8;
            float2 p0 = unp2(acc[i][0]), p1 = unp2(acc[i][1]);
            float2 p2 = unp2(acc[i][2]), p3 = unp2(acc[i][3]);
            red4(ap,     (p0.x + bb2[0]) * c * h0.x, (p0.y + bb2[1]) * c * h0.y,
                         (p1.x + bb2[2]) * c * h0.z, (p1.y + bb2[3]) * c * h0.w);
            red4(ap + 4, (p2.x + bb2[4]) * c * h1.x, (p2.y + bb2[5]) * c * h1.y,
                         (p3.x + bb2[6]) * c * h1.z, (p3.y + bb2[7]) * c * h1.w);
        }
        __syncthreads();
    }
}

// ---------------------------------------------------------------------------
extern "C" void kernel_launch(void* const* d_in, const int* in_sizes, int n_in,
                              void* d_out, int out_size)
{
    const float* x   = (const float*)d_in[0];
    const int*   ei  = (const int*)  d_in[1];
    const float* ew  = (const float*)d_in[2];
    const float* ea  = (const float*)d_in[3];
    const float* mw1 = (const float*)d_in[4];
    const float* mb1 = (const float*)d_in[5];
    const float* mw2 = (const float*)d_in[6];
    const float* mb2 = (const float*)d_in[7];
    const float* l1w = (const float*)d_in[8];
    const float* l2w = (const float*)d_in[9];
    const float* l2b = (const float*)d_in[10];
    const float* lw  = (const float*)d_in[11];
    const float* lb  = (const float*)d_in[12];
    float* out = (float*)d_out;

    const int N = in_sizes[0] / 128;
    const int E = in_sizes[1] / 2;

    void* p;
    cudaGetSymbolAddress(&p, g_h);   float* h_buf   = (float*)p;
    cudaGetSymbolAddress(&p, g_agg); float* agg_buf = (float*)p;
    cudaGetSymbolAddress(&p, g_h2);  float* h2_buf  = (float*)p;

    int sms = 148;
    cudaDeviceGetAttribute(&sms, cudaDevAttrMultiProcessorCount, 0);

    const size_t smemG = (size_t)2 * 128 * 132 * sizeof(float);
    const size_t smemE = (size_t)(6656 + 6600 + 16896 + 16896 + 128) * 4 + 256 * 4;

    cudaFuncSetAttribute(gemm128_kernel, cudaFuncAttributeMaxDynamicSharedMemorySize, (int)smemG);
    cudaFuncSetAttribute(edge_kernel,    cudaFuncAttributeMaxDynamicSharedMemorySize, (int)smemE);

    const int nb     = (N + MT - 1) / MT;
    const int nTiles = (E + MT - 1) / MT;

    gemm128_kernel<<<nb, NTH, smemG>>>(x, l1w, nullptr, h_buf, N, 0, agg_buf);
    edge_kernel<<<sms, NTH, smemE>>>(ea, ei, ew, mw1, mb1, mw2, mb2, h_buf, agg_buf, E, nTiles);
    gemm128_kernel<<<nb, NTH, smemG>>>(agg_buf, l2w, l2b, h2_buf, N, 1, nullptr);
    gemm128_kernel<<<nb, NTH, smemG>>>(h2_buf, lw, lb, out, N, 0, nullptr);
}